// round 8
// baseline (speedup 1.0000x reference)
#include <cuda_runtime.h>
#include <cstdint>

// Problem constants
#define Bc    2
#define Nc    128
#define Sc    4
#define DGc   8
#define CINc  4
#define COUTc 8
#define HIDc  32

// Static smem layout (float offsets). ALL weights non-duplicated, input-major
// [c][k][o]; all weights & biases pre-scaled by 0.5 at staging (silu trick).
#define KYW1t 0        // [c][k2][o]   256
#define KGW1t 256      // [c][k8][o]   1024
#define KYB1o 1280     // [c][o]       128
#define KGB1o 1408     // 128
#define KYW2t 1536     // [c][k32][o]  4096
#define KGW2t 5632     // 4096
#define KYB2o 9728     // 128
#define KGB2o 9856     // 128
#define KYW3o 9984     // 128
#define KGW3o 10112    // 128
#define KYB3o 10240    // 4
#define KGB3o 10244    // 4
#define WOUTo 10248    // 32
#define SREDo 10280    // 64
#define SWTOT 10344

typedef unsigned long long u64;

__device__ __forceinline__ u64 pk2(float lo, float hi) {
    u64 r; asm("mov.b64 %0, {%1, %2};" : "=l"(r) : "f"(lo), "f"(hi)); return r;
}
__device__ __forceinline__ void upk2(u64 v, float& lo, float& hi) {
    asm("mov.b64 {%0, %1}, %2;" : "=f"(lo), "=f"(hi) : "l"(v));
}
__device__ __forceinline__ u64 fma2(u64 a, u64 b, u64 c) {
    u64 d; asm("fma.rn.f32x2 %0, %1, %2, %3;" : "=l"(d) : "l"(a), "l"(b), "l"(c)); return d;
}
__device__ __forceinline__ u64 add2(u64 a, u64 b) {
    u64 d; asm("add.rn.f32x2 %0, %1, %2;" : "=l"(d) : "l"(a), "l"(b)); return d;
}
__device__ __forceinline__ float ex2f(float x) {
    float r; asm("ex2.approx.f32 %0, %1;" : "=f"(r) : "f"(x)); return r;
}
__device__ __forceinline__ float tanhf_a(float x) {
    float r; asm("tanh.approx.f32 %0, %1;" : "=f"(r) : "f"(x)); return r;
}

#define LOG2E 1.4426950408889634f

// Pre-scaled silu: input acc holds x/2 (weights pre-scaled by 0.5).
// silu(x) = (x/2)(1 + tanh(x/2)) = fma(acc, tanh(acc), acc). 1 fma-pipe + 2 MUFU.
__device__ __forceinline__ u64 silu2p(u64 acc) {
    float a, b; upk2(acc, a, b);
    u64 tp = pk2(tanhf_a(a), tanhf_a(b));
    return fma2(acc, tp, acc);
}
__device__ __forceinline__ float silu_fp(float acc) {   // acc = x/2
    return fmaf(acc, tanhf_a(acc), acc);
}

// Fused layers 2+3. hpA/hpB hold output-packed post-silu activations:
// hpA[p] = (h[2p](A), h[2p+1](A)). Weights pre-scaled; result is true silu(k).
__device__ __forceinline__ void mlp23(const u64* hpA, const u64* hpB,
                                      const float* __restrict__ w2,
                                      const float* __restrict__ b2,
                                      const float* __restrict__ w3,
                                      float b3, float& kA, float& kB)
{
    u64 tA0 = pk2(0.f, 0.f), tA1 = pk2(0.f, 0.f);
    u64 tB0 = pk2(0.f, 0.f), tB1 = pk2(0.f, 0.f);

    #pragma unroll 1
    for (int ch = 0; ch < 2; ++ch) {
        u64 aA[8], aB[8];
        {
            const ulonglong2* bb = reinterpret_cast<const ulonglong2*>(b2 + ch*16);
            ulonglong2 b0 = bb[0], b1v = bb[1], b2v = bb[2], b3v = bb[3];
            aA[0]=b0.x;  aA[1]=b0.y;  aA[2]=b1v.x; aA[3]=b1v.y;
            aA[4]=b2v.x; aA[5]=b2v.y; aA[6]=b3v.x; aA[7]=b3v.y;
            aB[0]=b0.x;  aB[1]=b0.y;  aB[2]=b1v.x; aB[3]=b1v.y;
            aB[4]=b2v.x; aB[5]=b2v.y; aB[6]=b3v.x; aB[7]=b3v.y;
        }
        const float* wkb = w2 + ch*16;
        #pragma unroll
        for (int p = 0; p < 16; ++p) {
            float ha0, ha1, hb0, hb1;
            upk2(hpA[p], ha0, ha1);
            upk2(hpB[p], hb0, hb1);
            // k = 2p
            {
                const u64 hAd = pk2(ha0, ha0);
                const u64 hBd = pk2(hb0, hb0);
                const ulonglong2* wv = reinterpret_cast<const ulonglong2*>(wkb + (2*p)*32);
                ulonglong2 w0 = wv[0], w1v = wv[1], w2v = wv[2], w3v = wv[3];
                aA[0] = fma2(hAd, w0.x,  aA[0]);
                aA[1] = fma2(hAd, w0.y,  aA[1]);
                aA[2] = fma2(hAd, w1v.x, aA[2]);
                aA[3] = fma2(hAd, w1v.y, aA[3]);
                aA[4] = fma2(hAd, w2v.x, aA[4]);
                aA[5] = fma2(hAd, w2v.y, aA[5]);
                aA[6] = fma2(hAd, w3v.x, aA[6]);
                aA[7] = fma2(hAd, w3v.y, aA[7]);
                aB[0] = fma2(hBd, w0.x,  aB[0]);
                aB[1] = fma2(hBd, w0.y,  aB[1]);
                aB[2] = fma2(hBd, w1v.x, aB[2]);
                aB[3] = fma2(hBd, w1v.y, aB[3]);
                aB[4] = fma2(hBd, w2v.x, aB[4]);
                aB[5] = fma2(hBd, w2v.y, aB[5]);
                aB[6] = fma2(hBd, w3v.x, aB[6]);
                aB[7] = fma2(hBd, w3v.y, aB[7]);
            }
            // k = 2p+1
            {
                const u64 hAd = pk2(ha1, ha1);
                const u64 hBd = pk2(hb1, hb1);
                const ulonglong2* wv = reinterpret_cast<const ulonglong2*>(wkb + (2*p+1)*32);
                ulonglong2 w0 = wv[0], w1v = wv[1], w2v = wv[2], w3v = wv[3];
                aA[0] = fma2(hAd, w0.x,  aA[0]);
                aA[1] = fma2(hAd, w0.y,  aA[1]);
                aA[2] = fma2(hAd, w1v.x, aA[2]);
                aA[3] = fma2(hAd, w1v.y, aA[3]);
                aA[4] = fma2(hAd, w2v.x, aA[4]);
                aA[5] = fma2(hAd, w2v.y, aA[5]);
                aA[6] = fma2(hAd, w3v.x, aA[6]);
                aA[7] = fma2(hAd, w3v.y, aA[7]);
                aB[0] = fma2(hBd, w0.x,  aB[0]);
                aB[1] = fma2(hBd, w0.y,  aB[1]);
                aB[2] = fma2(hBd, w1v.x, aB[2]);
                aB[3] = fma2(hBd, w1v.y, aB[3]);
                aB[4] = fma2(hBd, w2v.x, aB[4]);
                aB[5] = fma2(hBd, w2v.y, aB[5]);
                aB[6] = fma2(hBd, w3v.x, aB[6]);
                aB[7] = fma2(hBd, w3v.y, aB[7]);
            }
        }
        // silu + fold into layer-3 dot; 4 independent chains. w3 pre-scaled.
        const ulonglong2* w3p = reinterpret_cast<const ulonglong2*>(w3 + ch*16);
        ulonglong2 p0 = w3p[0], p1 = w3p[1], p2 = w3p[2], p3 = w3p[3];
        tA0 = fma2(silu2p(aA[0]), p0.x, tA0);
        tB0 = fma2(silu2p(aB[0]), p0.x, tB0);
        tA1 = fma2(silu2p(aA[1]), p0.y, tA1);
        tB1 = fma2(silu2p(aB[1]), p0.y, tB1);
        tA0 = fma2(silu2p(aA[2]), p1.x, tA0);
        tB0 = fma2(silu2p(aB[2]), p1.x, tB0);
        tA1 = fma2(silu2p(aA[3]), p1.y, tA1);
        tB1 = fma2(silu2p(aB[3]), p1.y, tB1);
        tA0 = fma2(silu2p(aA[4]), p2.x, tA0);
        tB0 = fma2(silu2p(aB[4]), p2.x, tB0);
        tA1 = fma2(silu2p(aA[5]), p2.y, tA1);
        tB1 = fma2(silu2p(aB[5]), p2.y, tB1);
        tA0 = fma2(silu2p(aA[6]), p3.x, tA0);
        tB0 = fma2(silu2p(aB[6]), p3.x, tB0);
        tA1 = fma2(silu2p(aA[7]), p3.y, tA1);
        tB1 = fma2(silu2p(aB[7]), p3.y, tB1);
    }
    float a0, a1, b0, b1v;
    upk2(add2(tA0, tA1), a0, a1);
    upk2(add2(tB0, tB1), b0, b1v);
    kA += silu_fp(a0 + a1 + b3);   // b3 pre-scaled; sum is x/2
    kB += silu_fp(b0 + b1v + b3);
}

__global__ __launch_bounds__(256, 2)
void ema_kernel(const float* __restrict__ g,
                const float* __restrict__ f,
                const int* __restrict__ mask,
                const float* __restrict__ kyW1, const float* __restrict__ kyb1,
                const float* __restrict__ kyW2, const float* __restrict__ kyb2,
                const float* __restrict__ kyW3, const float* __restrict__ kyb3,
                const float* __restrict__ kgW1, const float* __restrict__ kgb1,
                const float* __restrict__ kgW2, const float* __restrict__ kgb2,
                const float* __restrict__ kgW3, const float* __restrict__ kgb3,
                const float* __restrict__ wout,
                float* __restrict__ out)
{
    __shared__ __align__(16) float sw[SWTOT];

    const int tid = threadIdx.x;

    // ---- stage weights: transpose to input-major, pre-scale by 0.5 ----
    {
        for (int idx = tid; idx < 4096; idx += 256) {
            int c = idx >> 10, o = (idx >> 5) & 31, k = idx & 31;
            int d = c * 1024 + k * 32 + o;
            sw[KYW2t + d] = 0.5f * kyW2[idx];
            sw[KGW2t + d] = 0.5f * kgW2[idx];
        }
        for (int idx = tid; idx < 1024; idx += 256) {
            int c = idx >> 8, o = (idx >> 3) & 31, k = idx & 7;
            sw[KGW1t + c * 256 + k * 32 + o] = 0.5f * kgW1[idx];
        }
        if (tid < 256) {
            int idx = tid;
            int c = idx >> 6, o = (idx >> 1) & 31, k = idx & 1;
            sw[KYW1t + c * 64 + k * 32 + o] = 0.5f * kyW1[idx];
        }
        for (int idx = tid; idx < 128; idx += 256) {
            sw[KYB1o + idx] = 0.5f * kyb1[idx];
            sw[KGB1o + idx] = 0.5f * kgb1[idx];
            sw[KYB2o + idx] = 0.5f * kyb2[idx];
            sw[KGB2o + idx] = 0.5f * kgb2[idx];
            sw[KYW3o + idx] = 0.5f * kyW3[idx];
            sw[KGW3o + idx] = 0.5f * kgW3[idx];
        }
        if (tid < 4) { sw[KYB3o + tid] = 0.5f * kyb3[tid]; sw[KGB3o + tid] = 0.5f * kgb3[tid]; }
        if (tid < 32) sw[WOUTo + tid] = wout[tid];
    }
    __syncthreads();

    // ---- decode query (b, i, s) ----
    const int bid = blockIdx.x;
    const int b   = bid >> 9;
    const int rem = bid & 511;
    const int i   = rem >> 2;
    const int s   = rem & 3;

    float fq[CINc];
    {
        const float* fqp = f + (((size_t)b * Nc + i) * Sc + s) * CINc;
        float4 v = *reinterpret_cast<const float4*>(fqp);
        fq[0] = v.x; fq[1] = v.y; fq[2] = v.z; fq[3] = v.w;
    }

    // ---- two keys per thread: A=(j0,t), B=(j0+64,t) ----
    const int j0 = tid >> 2;
    const int t  = tid & 3;
    const int j1 = j0 + 64;

    u64 gvp[DGc];   // (gA, gB) packed per feature
    {
        const float* gp = g + ((((((size_t)b * Nc + i) * Nc + j0) * Sc + s) * Sc) + t) * DGc;
        float4 g0 = *reinterpret_cast<const float4*>(gp);
        float4 g1 = *reinterpret_cast<const float4*>(gp + 4);
        const float* gp2 = gp + (size_t)64 * Sc * Sc * DGc;
        float4 h0 = *reinterpret_cast<const float4*>(gp2);
        float4 h1 = *reinterpret_cast<const float4*>(gp2 + 4);
        gvp[0] = pk2(g0.x, h0.x); gvp[1] = pk2(g0.y, h0.y);
        gvp[2] = pk2(g0.z, h0.z); gvp[3] = pk2(g0.w, h0.w);
        gvp[4] = pk2(g1.x, h1.x); gvp[5] = pk2(g1.y, h1.y);
        gvp[6] = pk2(g1.z, h1.z); gvp[7] = pk2(g1.w, h1.w);
    }

    const bool mkA = mask[((size_t)b * Nc + j0) * Sc + t] != 0;
    const bool mkB = mask[((size_t)b * Nc + j1) * Sc + t] != 0;

    float fkA[CINc], fkB[CINc];
    {
        const float* p0 = f + (((size_t)b * Nc + j0) * Sc + t) * CINc;
        float4 v = *reinterpret_cast<const float4*>(p0);
        fkA[0]=v.x; fkA[1]=v.y; fkA[2]=v.z; fkA[3]=v.w;
        const float* p1 = f + (((size_t)b * Nc + j1) * Sc + t) * CINc;
        float4 w = *reinterpret_cast<const float4*>(p1);
        fkB[0]=w.x; fkB[1]=w.y; fkB[2]=w.z; fkB[3]=w.w;
    }

    float num[CINc], den[CINc];

    #pragma unroll 1
    for (int c = 0; c < CINc; ++c) {
        float kAt = 0.f, kBt = 0.f;
        u64 hpA[16], hpB[16];   // output-packed activations per position

        #pragma unroll 1
        for (int m = 0; m < 2; ++m) {
            // ===== layer 1 (output-packed, non-dup weights) =====
            if (m == 0) {
                const float* w1 = sw + KYW1t + c * 64;   // [k2][o]
                const float* b1 = sw + KYB1o + c * 32;
                const u64 fqd  = pk2(fq[c],  fq[c]);
                const u64 fkAd = pk2(fkA[c], fkA[c]);
                const u64 fkBd = pk2(fkB[c], fkB[c]);
                #pragma unroll
                for (int q = 0; q < 8; ++q) {
                    ulonglong2 w0 = *reinterpret_cast<const ulonglong2*>(w1 + 4*q);       // k=0 (key)
                    ulonglong2 wq = *reinterpret_cast<const ulonglong2*>(w1 + 32 + 4*q);  // k=1 (query)
                    ulonglong2 bv = *reinterpret_cast<const ulonglong2*>(b1 + 4*q);
                    u64 t0 = fma2(fqd, wq.x, bv.x);
                    u64 t1 = fma2(fqd, wq.y, bv.y);
                    hpA[2*q]   = fma2(fkAd, w0.x, t0);
                    hpA[2*q+1] = fma2(fkAd, w0.y, t1);
                    hpB[2*q]   = fma2(fkBd, w0.x, t0);
                    hpB[2*q+1] = fma2(fkBd, w0.y, t1);
                }
            } else {
                const float* w1 = sw + KGW1t + c * 256;   // [k8][o]
                const float* b1 = sw + KGB1o + c * 32;
                #pragma unroll
                for (int q = 0; q < 8; ++q) {
                    ulonglong2 bv = *reinterpret_cast<const ulonglong2*>(b1 + 4*q);
                    hpA[2*q] = bv.x; hpA[2*q+1] = bv.y;
                    hpB[2*q] = bv.x; hpB[2*q+1] = bv.y;
                }
                #pragma unroll
                for (int k = 0; k < DGc; ++k) {
                    float ga, gb; upk2(gvp[k], ga, gb);
                    const u64 gad = pk2(ga, ga);
                    const u64 gbd = pk2(gb, gb);
                    const float* wk = w1 + k * 32;
                    #pragma unroll
                    for (int q = 0; q < 8; ++q) {
                        ulonglong2 wv = *reinterpret_cast<const ulonglong2*>(wk + 4*q);
                        hpA[2*q]   = fma2(gad, wv.x, hpA[2*q]);
                        hpA[2*q+1] = fma2(gad, wv.y, hpA[2*q+1]);
                        hpB[2*q]   = fma2(gbd, wv.x, hpB[2*q]);
                        hpB[2*q+1] = fma2(gbd, wv.y, hpB[2*q+1]);
                    }
                }
            }
            // silu (pre-scaled form)
            #pragma unroll
            for (int p = 0; p < 16; ++p) {
                hpA[p] = silu2p(hpA[p]);
                hpB[p] = silu2p(hpB[p]);
            }

            // ===== fused layers 2+3 =====
            mlp23(hpA, hpB,
                  sw + (m ? KGW2t : KYW2t) + c * 1024,
                  sw + (m ? KGB2o : KYB2o) + c * HIDc,
                  sw + (m ? KGW3o : KYW3o) + c * HIDc,
                  sw[(m ? KGB3o : KYB3o) + c], kAt, kBt);
        }

        const float eA = mkA ? ex2f(LOG2E * kAt) : 0.0f;
        const float eB = mkB ? ex2f(LOG2E * kBt) : 0.0f;
        den[c] = eA + eB;
        num[c] = fmaf(eA, fkA[c], eB * fkB[c]);
    }

    // ---- reduce over 256 threads (8 warps) ----
    #pragma unroll
    for (int c = 0; c < CINc; ++c) {
        #pragma unroll
        for (int off = 16; off > 0; off >>= 1) {
            num[c] += __shfl_xor_sync(0xFFFFFFFFu, num[c], off);
            den[c] += __shfl_xor_sync(0xFFFFFFFFu, den[c], off);
        }
    }
    const int wid = tid >> 5;
    const int lid = tid & 31;
    if (lid == 0) {
        #pragma unroll
        for (int c = 0; c < CINc; ++c) {
            sw[SREDo + wid * 8 + c]     = num[c];
            sw[SREDo + wid * 8 + 4 + c] = den[c];
        }
    }
    __syncthreads();

    if (tid < COUTc) {
        const int o = tid;
        const float mq = (mask[((size_t)b * Nc + i) * Sc + s] != 0) ? 1.0f : 0.0f;
        float acc = 0.0f;
        #pragma unroll
        for (int c = 0; c < CINc; ++c) {
            float n = 0.0f, d = 0.0f;
            #pragma unroll
            for (int w = 0; w < 8; ++w) {
                n += sw[SREDo + w * 8 + c];
                d += sw[SREDo + w * 8 + 4 + c];
            }
            const float cf = (fq[c] + n / d) * mq;
            acc = fmaf(cf, sw[WOUTo + o * CINc + c], acc);
        }
        out[(((size_t)b * Nc + i) * Sc + s) * COUTc + o] = acc;
    }
}

extern "C" void kernel_launch(void* const* d_in, const int* in_sizes, int n_in,
                              void* d_out, int out_size)
{
    const float* g    = (const float*)d_in[0];
    const float* f    = (const float*)d_in[1];
    const int*   mask = (const int*)d_in[2];
    const float* kyW1 = (const float*)d_in[3];
    const float* kyb1 = (const float*)d_in[4];
    const float* kyW2 = (const float*)d_in[5];
    const float* kyb2 = (const float*)d_in[6];
    const float* kyW3 = (const float*)d_in[7];
    const float* kyb3 = (const float*)d_in[8];
    const float* kgW1 = (const float*)d_in[9];
    const float* kgb1 = (const float*)d_in[10];
    const float* kgW2 = (const float*)d_in[11];
    const float* kgb2 = (const float*)d_in[12];
    const float* kgW3 = (const float*)d_in[13];
    const float* kgb3 = (const float*)d_in[14];
    const float* wout = (const float*)d_in[15];
    float* out = (float*)d_out;

    ema_kernel<<<Bc * Nc * Sc, 256>>>(g, f, mask,
                                      kyW1, kyb1, kyW2, kyb2, kyW3, kyb3,
                                      kgW1, kgb1, kgW2, kgb2, kgW3, kgb3,
                                      wout, out);
}